// round 16
// baseline (speedup 1.0000x reference)
#include <cuda_runtime.h>
#include <cuda_bf16.h>
#include <math.h>
#include <stdint.h>

typedef unsigned long long ull;

#define TT 512
#define BB 256
#define OBSD 512
#define HH 256
#define H3 768
#define MM (TT*BB)          // 131072
#define BIGC 1e10f
#define AMAX 48

// hgemm dynamic smem layout (elements, per buffer)
#define HG_BUF   15360
#define HG_ALO   5120
#define HG_BHI   10240
#define HG_BLO   12800
#define HG_SMEM  (2 * HG_BUF * 2)   // 61440 B

// wave_fused dynamic smem layout (elements, per buffer)
#define WV_BUF   17920
#define WV_ALO   5120
#define WV_BHI   10240
#define WV_BLO   14080
#define WV_SMEM  (2 * WV_BUF * 2)   // 71680 B

// ---- output layout ----
static const size_t OFF_LC1  = 65536;
static const size_t OFF_LC2  = OFF_LC1  + (size_t)MM*32;
static const size_t OFF_MC   = OFF_LC2  + (size_t)MM*32;
static const size_t OFF_HINT = OFF_MC   + (size_t)MM*16;
static const size_t OFF_CRIT = OFF_HINT + (size_t)MM*64;

// ---- scratch ----
__device__ float g_emb[(size_t)MM*HH];        // hosts embHi/embLo bf16 halves
__device__ float g_gi [(size_t)MM*H3];
__device__ float g_yx [((size_t)MM+BB)*HH];
__device__ float g_a  [(size_t)MM*HH];
__device__ float g_crit8[(size_t)MM*8];
__device__ float g_bheadP[256];
__device__ float g_bac[512];

// bf16 hi/lo transposed weights [N][K]
__device__ __nv_bfloat16 g_WembHi[HH*OBSD], g_WembLo[HH*OBSD];
__device__ __nv_bfloat16 g_WiHi [H3*HH],   g_WiLo [H3*HH];
__device__ __nv_bfloat16 g_WacHi[512*HH],  g_WacLo[512*HH];
__device__ __nv_bfloat16 g_WhdHi[256*HH],  g_WhdLo[256*HH];
__device__ __nv_bfloat16 g_WhHi [H3*HH],   g_WhLo [H3*HH];

__device__ int g_list[MM];
__device__ int g_offs[513];

// ---- math helpers ----
__device__ __forceinline__ float sigm(float x) {
    return __fdividef(1.f, 1.f + __expf(-x));
}
__device__ __forceinline__ float tanh_fast(float x) {
    return 1.f - __fdividef(2.f, __expf(2.f * x) + 1.f);
}

// ---- mma.sync helpers ----
__device__ __forceinline__ uint32_t smem_u32(const void* p) {
    return (uint32_t)__cvta_generic_to_shared(p);
}
__device__ __forceinline__ void ldsm4(uint32_t* r, uint32_t addr) {
    asm volatile("ldmatrix.sync.aligned.m8n8.x4.shared.b16 {%0,%1,%2,%3}, [%4];"
                 : "=r"(r[0]), "=r"(r[1]), "=r"(r[2]), "=r"(r[3]) : "r"(addr));
}
__device__ __forceinline__ void mma_bf16(float* d, const uint32_t* a, const uint32_t* b) {
    asm volatile(
        "mma.sync.aligned.m16n8k16.row.col.f32.bf16.bf16.f32 "
        "{%0,%1,%2,%3}, {%4,%5,%6,%7}, {%8,%9}, {%0,%1,%2,%3};"
        : "+f"(d[0]), "+f"(d[1]), "+f"(d[2]), "+f"(d[3])
        : "r"(a[0]), "r"(a[1]), "r"(a[2]), "r"(a[3]), "r"(b[0]), "r"(b[1]));
}
__device__ __forceinline__ void split2(float x, float y, __nv_bfloat162& hi, __nv_bfloat162& lo) {
    hi = __floats2bfloat162_rn(x, y);
    lo = __floats2bfloat162_rn(x - __bfloat162float(hi.x), y - __bfloat162float(hi.y));
}

// =====================================================================
// Dense tensor-core bf16-split GEMM (double-buffered).
// MODE 2: head mask+scatter; 4: Wa+c1 merged; 5: relu + split-store
// (emb -> bf16 hi/lo, C = hi base, outp = lo base).
// =====================================================================
template <int MODE>
__global__ __launch_bounds__(256, 2) void hgemm(
    const float* __restrict__ A,
    const __nv_bfloat16* __restrict__ BhiT, const __nv_bfloat16* __restrict__ BloT,
    const float* __restrict__ bias, float* __restrict__ C, int N, int K,
    const int* __restrict__ al1, const int* __restrict__ al2,
    const int* __restrict__ amc, const int* __restrict__ aht,
    const float* __restrict__ w2, float* __restrict__ outp)
{
    extern __shared__ __nv_bfloat16 sm[];

    const int tid = threadIdx.x;
    const int lane = tid & 31;
    const int wid = tid >> 5;
    const int wm = (wid & 3) * 32;
    const int wn = (wid >> 2) * 32;
    const int m0 = blockIdx.y * 128;
    const int n0 = blockIdx.x * 64;

    const int ar = tid >> 3, ac4 = tid & 7;
    const int br = tid >> 2, bs = tid & 3;

    float acc[2][4][4];
#pragma unroll
    for (int mt = 0; mt < 2; mt++)
#pragma unroll
        for (int nt = 0; nt < 4; nt++)
#pragma unroll
            for (int q = 0; q < 4; q++) acc[mt][nt][q] = 0.f;

    float4 ra[4]; uint4 rbh, rbl;
    auto loadg = [&](int kc) {
#pragma unroll
        for (int u = 0; u < 4; u++)
            ra[u] = *(const float4*)&A[(size_t)(m0 + ar + u * 32) * K + kc + ac4 * 4];
        rbh = *(const uint4*)&BhiT[(size_t)(n0 + br) * K + kc + bs * 8];
        rbl = *(const uint4*)&BloT[(size_t)(n0 + br) * K + kc + bs * 8];
    };
    auto storesm = [&](int p) {
        __nv_bfloat16* buf = sm + p * HG_BUF;
#pragma unroll
        for (int u = 0; u < 4; u++) {
            float4 v = ra[u];
            __nv_bfloat162 h0, l0, h1, l1;
            split2(v.x, v.y, h0, l0);
            split2(v.z, v.w, h1, l1);
            union { __nv_bfloat162 b2[2]; ull u64; } ph, pl;
            ph.b2[0] = h0; ph.b2[1] = h1;
            pl.b2[0] = l0; pl.b2[1] = l1;
            *(ull*)&buf[(ar + u * 32) * 40 + ac4 * 4] = ph.u64;
            *(ull*)&buf[HG_ALO + (ar + u * 32) * 40 + ac4 * 4] = pl.u64;
        }
        *(uint4*)&buf[HG_BHI + br * 40 + bs * 8] = rbh;
        *(uint4*)&buf[HG_BLO + br * 40 + bs * 8] = rbl;
    };

    loadg(0);
    storesm(0);
    __syncthreads();

    const int nc = K >> 5;
    for (int i = 0; i < nc; i++) {
        const bool more = (i + 1) < nc;
        if (more) loadg((i + 1) * 32);

        const __nv_bfloat16* buf = sm + (i & 1) * HG_BUF;
#pragma unroll
        for (int kk = 0; kk < 32; kk += 16) {
            uint32_t ah[2][4], al[2][4], bh[4][2], bl[4][2];
            const int arow = (lane & 15);
            const int acol = kk + ((lane >> 4) << 3);
#pragma unroll
            for (int mt = 0; mt < 2; mt++) {
                ldsm4(ah[mt], smem_u32(&buf[(wm + mt * 16 + arow) * 40 + acol]));
                ldsm4(al[mt], smem_u32(&buf[HG_ALO + (wm + mt * 16 + arow) * 40 + acol]));
            }
            const int brow = ((lane >> 4) << 3) + (lane & 7);
            const int bcol = kk + ((lane >> 3) & 1) * 8;
#pragma unroll
            for (int half = 0; half < 2; half++) {
                uint32_t t4[4];
                ldsm4(t4, smem_u32(&buf[HG_BHI + (wn + half * 16 + brow) * 40 + bcol]));
                bh[half*2+0][0] = t4[0]; bh[half*2+0][1] = t4[1];
                bh[half*2+1][0] = t4[2]; bh[half*2+1][1] = t4[3];
                ldsm4(t4, smem_u32(&buf[HG_BLO + (wn + half * 16 + brow) * 40 + bcol]));
                bl[half*2+0][0] = t4[0]; bl[half*2+0][1] = t4[1];
                bl[half*2+1][0] = t4[2]; bl[half*2+1][1] = t4[3];
            }
#pragma unroll
            for (int mt = 0; mt < 2; mt++)
#pragma unroll
                for (int nt = 0; nt < 4; nt++) {
                    mma_bf16(acc[mt][nt], ah[mt], bh[nt]);
                    mma_bf16(acc[mt][nt], al[mt], bh[nt]);
                    mma_bf16(acc[mt][nt], ah[mt], bl[nt]);
                }
        }

        if (more) {
            storesm((i + 1) & 1);
            __syncthreads();
        }
    }

    if (MODE == 5) {
        // relu + bf16 hi/lo split store (emb)
        __nv_bfloat16* Chi = (__nv_bfloat16*)C;
        __nv_bfloat16* Clo = (__nv_bfloat16*)outp;
#pragma unroll
        for (int mt = 0; mt < 2; mt++) {
#pragma unroll
            for (int nt = 0; nt < 4; nt++) {
                int r = m0 + wm + mt * 16 + (lane >> 2);
                int cI = n0 + wn + nt * 8 + (lane & 3) * 2;
                float bx = bias[cI], by = bias[cI + 1];
                float x0 = fmaxf(acc[mt][nt][0] + bx, 0.f);
                float y0 = fmaxf(acc[mt][nt][1] + by, 0.f);
                float x1 = fmaxf(acc[mt][nt][2] + bx, 0.f);
                float y1 = fmaxf(acc[mt][nt][3] + by, 0.f);
                __nv_bfloat162 h, l;
                split2(x0, y0, h, l);
                *(__nv_bfloat162*)&Chi[(size_t)r * N + cI] = h;
                *(__nv_bfloat162*)&Clo[(size_t)r * N + cI] = l;
                split2(x1, y1, h, l);
                *(__nv_bfloat162*)&Chi[(size_t)(r + 8) * N + cI] = h;
                *(__nv_bfloat162*)&Clo[(size_t)(r + 8) * N + cI] = l;
            }
        }
    } else if (MODE == 2) {
        auto emit = [&](int m, int n, float x, float y) {
            if (n < 32) {
                size_t o = (size_t)m * 32 + n;
                outp[OFF_LC1 + o]     = x - (1.f - (float)al1[o]) * BIGC;
                outp[OFF_LC1 + o + 1] = y - (1.f - (float)al1[o + 1]) * BIGC;
            } else if (n < 64) {
                size_t o = (size_t)m * 32 + (n - 32);
                outp[OFF_LC2 + o]     = x - (1.f - (float)al2[o]) * BIGC;
                outp[OFF_LC2 + o + 1] = y - (1.f - (float)al2[o + 1]) * BIGC;
            } else if (n < 80) {
                size_t o = (size_t)m * 16 + (n - 64);
                outp[OFF_MC + o]      = x - (1.f - (float)amc[o]) * BIGC;
                outp[OFF_MC + o + 1]  = y - (1.f - (float)amc[o + 1]) * BIGC;
            } else if (n < 144) {
                size_t o = (size_t)m * 64 + (n - 80);
                outp[OFF_HINT + o]     = x - (1.f - (float)aht[o]) * BIGC;
                outp[OFF_HINT + o + 1] = y - (1.f - (float)aht[o + 1]) * BIGC;
            }
        };
#pragma unroll
        for (int mt = 0; mt < 2; mt++) {
#pragma unroll
            for (int nt = 0; nt < 4; nt++) {
                int r = m0 + wm + mt * 16 + (lane >> 2);
                int cI = n0 + wn + nt * 8 + (lane & 3) * 2;
                float bx = bias[cI], by = bias[cI + 1];
                emit(r,     cI, acc[mt][nt][0] + bx, acc[mt][nt][1] + by);
                emit(r + 8, cI, acc[mt][nt][2] + bx, acc[mt][nt][3] + by);
            }
        }
    } else {   // MODE 4
        if (n0 < 256) {
#pragma unroll
            for (int mt = 0; mt < 2; mt++) {
#pragma unroll
                for (int nt = 0; nt < 4; nt++) {
                    int r = m0 + wm + mt * 16 + (lane >> 2);
                    int cI = n0 + wn + nt * 8 + (lane & 3) * 2;
                    float bx = bias[cI], by = bias[cI + 1];
                    float x0 = fmaxf(acc[mt][nt][0] + bx, 0.f);
                    float y0 = fmaxf(acc[mt][nt][1] + by, 0.f);
                    float x1 = fmaxf(acc[mt][nt][2] + bx, 0.f);
                    float y1 = fmaxf(acc[mt][nt][3] + by, 0.f);
                    *(float2*)&C[(size_t)r * 256 + cI] = make_float2(x0, y0);
                    *(float2*)&C[(size_t)(r + 8) * 256 + cI] = make_float2(x1, y1);
                }
            }
        } else {
#pragma unroll
            for (int mt = 0; mt < 2; mt++) {
#pragma unroll
                for (int rr = 0; rr < 2; rr++) {
                    float partial = 0.f;
#pragma unroll
                    for (int nt = 0; nt < 4; nt++) {
                        int cI = n0 + wn + nt * 8 + (lane & 3) * 2;
                        float x = fmaxf(acc[mt][nt][rr*2+0] + bias[cI], 0.f);
                        float y = fmaxf(acc[mt][nt][rr*2+1] + bias[cI+1], 0.f);
                        partial = fmaf(x, w2[cI - 256], partial);
                        partial = fmaf(y, w2[cI - 255], partial);
                    }
                    partial += __shfl_xor_sync(0xffffffffu, partial, 1);
                    partial += __shfl_xor_sync(0xffffffffu, partial, 2);
                    if ((lane & 3) == 0) {
                        int r = m0 + wm + mt * 16 + (lane >> 2) + rr * 8;
                        g_crit8[(size_t)r * 8 + (blockIdx.x - 4) * 2 + (wid >> 2)] = partial;
                    }
                }
            }
        }
    }
}

// =====================================================================
// hgemm_ps: dense GEMM with PRE-SPLIT bf16 A (hi/lo). Plain store.
// Used for gi = emb @ Wi + bi (A = embHi/embLo).
// =====================================================================
__global__ __launch_bounds__(256, 2) void hgemm_ps(
    const __nv_bfloat16* __restrict__ AHi, const __nv_bfloat16* __restrict__ ALo,
    const __nv_bfloat16* __restrict__ BhiT, const __nv_bfloat16* __restrict__ BloT,
    const float* __restrict__ bias, float* __restrict__ C, int N, int K)
{
    extern __shared__ __nv_bfloat16 sm[];

    const int tid = threadIdx.x;
    const int lane = tid & 31;
    const int wid = tid >> 5;
    const int wm = (wid & 3) * 32;
    const int wn = (wid >> 2) * 32;
    const int m0 = blockIdx.y * 128;
    const int n0 = blockIdx.x * 64;

    const int ar = tid >> 3, ac4 = tid & 7;
    const int br = tid >> 2, bs = tid & 3;

    float acc[2][4][4];
#pragma unroll
    for (int mt = 0; mt < 2; mt++)
#pragma unroll
        for (int nt = 0; nt < 4; nt++)
#pragma unroll
            for (int q = 0; q < 4; q++) acc[mt][nt][q] = 0.f;

    ull rah[4], ral[4]; uint4 rbh, rbl;
    auto loadg = [&](int kc) {
#pragma unroll
        for (int u = 0; u < 4; u++) {
            size_t off = (size_t)(m0 + ar + u * 32) * K + kc + ac4 * 4;
            rah[u] = *(const ull*)&AHi[off];
            ral[u] = *(const ull*)&ALo[off];
        }
        rbh = *(const uint4*)&BhiT[(size_t)(n0 + br) * K + kc + bs * 8];
        rbl = *(const uint4*)&BloT[(size_t)(n0 + br) * K + kc + bs * 8];
    };
    auto storesm = [&](int p) {
        __nv_bfloat16* buf = sm + p * HG_BUF;
#pragma unroll
        for (int u = 0; u < 4; u++) {
            *(ull*)&buf[(ar + u * 32) * 40 + ac4 * 4] = rah[u];
            *(ull*)&buf[HG_ALO + (ar + u * 32) * 40 + ac4 * 4] = ral[u];
        }
        *(uint4*)&buf[HG_BHI + br * 40 + bs * 8] = rbh;
        *(uint4*)&buf[HG_BLO + br * 40 + bs * 8] = rbl;
    };

    loadg(0);
    storesm(0);
    __syncthreads();

    const int nc = K >> 5;
    for (int i = 0; i < nc; i++) {
        const bool more = (i + 1) < nc;
        if (more) loadg((i + 1) * 32);

        const __nv_bfloat16* buf = sm + (i & 1) * HG_BUF;
#pragma unroll
        for (int kk = 0; kk < 32; kk += 16) {
            uint32_t ah[2][4], al[2][4], bh[4][2], bl[4][2];
            const int arow = (lane & 15);
            const int acol = kk + ((lane >> 4) << 3);
#pragma unroll
            for (int mt = 0; mt < 2; mt++) {
                ldsm4(ah[mt], smem_u32(&buf[(wm + mt * 16 + arow) * 40 + acol]));
                ldsm4(al[mt], smem_u32(&buf[HG_ALO + (wm + mt * 16 + arow) * 40 + acol]));
            }
            const int brow = ((lane >> 4) << 3) + (lane & 7);
            const int bcol = kk + ((lane >> 3) & 1) * 8;
#pragma unroll
            for (int half = 0; half < 2; half++) {
                uint32_t t4[4];
                ldsm4(t4, smem_u32(&buf[HG_BHI + (wn + half * 16 + brow) * 40 + bcol]));
                bh[half*2+0][0] = t4[0]; bh[half*2+0][1] = t4[1];
                bh[half*2+1][0] = t4[2]; bh[half*2+1][1] = t4[3];
                ldsm4(t4, smem_u32(&buf[HG_BLO + (wn + half * 16 + brow) * 40 + bcol]));
                bl[half*2+0][0] = t4[0]; bl[half*2+0][1] = t4[1];
                bl[half*2+1][0] = t4[2]; bl[half*2+1][1] = t4[3];
            }
#pragma unroll
            for (int mt = 0; mt < 2; mt++)
#pragma unroll
                for (int nt = 0; nt < 4; nt++) {
                    mma_bf16(acc[mt][nt], ah[mt], bh[nt]);
                    mma_bf16(acc[mt][nt], al[mt], bh[nt]);
                    mma_bf16(acc[mt][nt], ah[mt], bl[nt]);
                }
        }

        if (more) {
            storesm((i + 1) & 1);
            __syncthreads();
        }
    }

#pragma unroll
    for (int mt = 0; mt < 2; mt++) {
#pragma unroll
        for (int nt = 0; nt < 4; nt++) {
            int r = m0 + wm + mt * 16 + (lane >> 2);
            int cI = n0 + wn + nt * 8 + (lane & 3) * 2;
            float bx = bias[cI], by = bias[cI + 1];
            *(float2*)&C[(size_t)r * N + cI] =
                make_float2(acc[mt][nt][0] + bx, acc[mt][nt][1] + by);
            *(float2*)&C[(size_t)(r + 8) * N + cI] =
                make_float2(acc[mt][nt][2] + bx, acc[mt][nt][3] + by);
        }
    }
}

__global__ void crit_final(const float* __restrict__ b2, float* __restrict__ out) {
    int m = blockIdx.x * 256 + threadIdx.x;
    const float4* p = (const float4*)&g_crit8[(size_t)m * 8];
    float4 v0 = p[0], v1 = p[1];
    out[OFF_CRIT + m] = v0.x + v0.y + v0.z + v0.w + v1.x + v1.y + v1.z + v1.w + b2[0];
}

// =====================================================================
// Fused wave kernel (double-buffered, R15 proven, unchanged).
// =====================================================================
__global__ __launch_bounds__(256, 2) void wave_fused(
    const __nv_bfloat16* __restrict__ WhHiT, const __nv_bfloat16* __restrict__ WhLoT,
    const float* __restrict__ bhn, int a)
{
    const int base = g_offs[a];
    const int cnt  = g_offs[a + 1] - base;
    const int m0 = blockIdx.y * 128;
    if (m0 >= cnt) return;
    const int j0 = blockIdx.x * 32;

    extern __shared__ __nv_bfloat16 sm[];

    const int tid = threadIdx.x;
    const int lane = tid & 31;
    const int wid = tid >> 5;
    const int wm = (wid & 3) * 32;
    const int wn = (wid >> 2) * 16;

    const int ar = tid >> 3, ac4 = tid & 7;
    int ridx[4];
#pragma unroll
    for (int u = 0; u < 4; u++) {
        int m = m0 + ar + u * 32;
        ridx[u] = g_list[base + (m < cnt ? m : cnt - 1)];
    }
    const int br0 = tid >> 2, bs0 = tid & 3;
    const int br1 = 64 + (tid >> 2), bs1 = tid & 3;
    const int bgr0 = (br0 >> 5) * HH + j0 + (br0 & 31);
    const int bgr1 = (br1 >> 5) * HH + j0 + (br1 & 31);

    float acc[3][2][2][4];
#pragma unroll
    for (int g = 0; g < 3; g++)
#pragma unroll
        for (int mt = 0; mt < 2; mt++)
#pragma unroll
            for (int nt = 0; nt < 2; nt++)
#pragma unroll
                for (int q = 0; q < 4; q++) acc[g][mt][nt][q] = 0.f;

    float4 ra[4]; uint4 rbh0, rbl0, rbh1, rbl1;
    auto loadg = [&](int kc) {
#pragma unroll
        for (int u = 0; u < 4; u++)
            ra[u] = *(const float4*)&g_yx[(size_t)ridx[u] * HH + kc + ac4 * 4];
        rbh0 = *(const uint4*)&WhHiT[(size_t)bgr0 * HH + kc + bs0 * 8];
        rbl0 = *(const uint4*)&WhLoT[(size_t)bgr0 * HH + kc + bs0 * 8];
        if (tid < 128) {
            rbh1 = *(const uint4*)&WhHiT[(size_t)bgr1 * HH + kc + bs1 * 8];
            rbl1 = *(const uint4*)&WhLoT[(size_t)bgr1 * HH + kc + bs1 * 8];
        }
    };
    auto storesm = [&](int p) {
        __nv_bfloat16* buf = sm + p * WV_BUF;
#pragma unroll
        for (int u = 0; u < 4; u++) {
            float4 v = ra[u];
            __nv_bfloat162 h0, l0, h1, l1;
            split2(v.x, v.y, h0, l0);
            split2(v.z, v.w, h1, l1);
            union { __nv_bfloat162 b2[2]; ull u64; } ph, pl;
            ph.b2[0] = h0; ph.b2[1] = h1;
            pl.b2[0] = l0; pl.b2[1] = l1;
            *(ull*)&buf[(ar + u * 32) * 40 + ac4 * 4] = ph.u64;
            *(ull*)&buf[WV_ALO + (ar + u * 32) * 40 + ac4 * 4] = pl.u64;
        }
        *(uint4*)&buf[WV_BHI + br0 * 40 + bs0 * 8] = rbh0;
        *(uint4*)&buf[WV_BLO + br0 * 40 + bs0 * 8] = rbl0;
        if (tid < 128) {
            *(uint4*)&buf[WV_BHI + br1 * 40 + bs1 * 8] = rbh1;
            *(uint4*)&buf[WV_BLO + br1 * 40 + bs1 * 8] = rbl1;
        }
    };

    loadg(0);
    storesm(0);
    __syncthreads();

    const int nc = HH >> 5;
    for (int i = 0; i < nc; i++) {
        const bool more = (i + 1) < nc;
        if (more) loadg((i + 1) * 32);

        const __nv_bfloat16* buf = sm + (i & 1) * WV_BUF;
#pragma unroll
        for (int kk = 0; kk < 32; kk += 16) {
            uint32_t ah[2][4], al[2][4];
            const int arow = (lane & 15);
            const int acol = kk + ((lane >> 4) << 3);
#pragma unroll
            for (int mt = 0; mt < 2; mt++) {
                ldsm4(ah[mt], smem_u32(&buf[(wm + mt * 16 + arow) * 40 + acol]));
                ldsm4(al[mt], smem_u32(&buf[WV_ALO + (wm + mt * 16 + arow) * 40 + acol]));
            }
            const int brow = ((lane >> 4) << 3) + (lane & 7);
            const int bcol = kk + ((lane >> 3) & 1) * 8;
#pragma unroll
            for (int g = 0; g < 3; g++) {
                uint32_t bh[4], bl[4];
                ldsm4(bh, smem_u32(&buf[WV_BHI + (g * 32 + wn + brow) * 40 + bcol]));
                ldsm4(bl, smem_u32(&buf[WV_BLO + (g * 32 + wn + brow) * 40 + bcol]));
#pragma unroll
                for (int mt = 0; mt < 2; mt++) {
                    mma_bf16(acc[g][mt][0], ah[mt], bh + 0);
                    mma_bf16(acc[g][mt][1], ah[mt], bh + 2);
                    mma_bf16(acc[g][mt][0], al[mt], bh + 0);
                    mma_bf16(acc[g][mt][1], al[mt], bh + 2);
                    mma_bf16(acc[g][mt][0], ah[mt], bl + 0);
                    mma_bf16(acc[g][mt][1], ah[mt], bl + 2);
                }
            }
        }

        if (more) {
            storesm((i + 1) & 1);
            __syncthreads();
        }
    }

    // fused GRU gate epilogue
#pragma unroll
    for (int mt = 0; mt < 2; mt++) {
#pragma unroll
        for (int nt = 0; nt < 2; nt++) {
            const int jj = j0 + wn + nt * 8 + (lane & 3) * 2;
            const float2 bh2 = *(const float2*)&bhn[jj];
#pragma unroll
            for (int rr = 0; rr < 2; rr++) {
                int m = m0 + wm + mt * 16 + (lane >> 2) + rr * 8;
                if (m >= cnt) continue;
                int idx = g_list[base + m];
                const float* gip = g_gi + (size_t)idx * H3;
                float2 gr2 = *(const float2*)&gip[jj];
                float2 gz2 = *(const float2*)&gip[HH + jj];
                float2 gn2 = *(const float2*)&gip[2 * HH + jj];
                float2 h2  = *(const float2*)&g_yx[(size_t)idx * HH + jj];
                float r0 = sigm(gr2.x + acc[0][mt][nt][rr*2+0]);
                float r1 = sigm(gr2.y + acc[0][mt][nt][rr*2+1]);
                float z0 = sigm(gz2.x + acc[1][mt][nt][rr*2+0]);
                float z1 = sigm(gz2.y + acc[1][mt][nt][rr*2+1]);
                float n0 = tanh_fast(gn2.x + r0 * (acc[2][mt][nt][rr*2+0] + bh2.x));
                float n1 = tanh_fast(gn2.y + r1 * (acc[2][mt][nt][rr*2+1] + bh2.y));
                float y0 = (1.f - z0) * n0 + z0 * h2.x;
                float y1 = (1.f - z1) * n1 + z1 * h2.y;
                *(float2*)&g_yx[(size_t)(idx + BB) * HH + jj] = make_float2(y0, y1);
            }
        }
    }
}

// =====================================================================
// Gate for wave 0 (membership = dones != 0)
// =====================================================================
__global__ void gate_wave0(const int* __restrict__ dones, const float* __restrict__ bhn) {
    int m = blockIdx.x * 16 + (threadIdx.x >> 4);
    if (dones[m] == 0) return;
    int jg = threadIdx.x & 15;
    const float* gip = g_gi + (size_t)m * H3;
    float* yp = g_yx + (size_t)(m + BB) * HH;
#pragma unroll 4
    for (int l = 0; l < 16; l++) {
        int j = l * 16 + jg;
        float r = sigm(gip[j]);
        float z = sigm(gip[HH + j]);
        float n = tanh_fast(gip[2 * HH + j] + r * bhn[j]);
        yp[j] = (1.f - z) * n;
    }
}

// =====================================================================
// Fused index build (ages >= 1 only)
// =====================================================================
__global__ __launch_bounds__(512) void build_index(const int* __restrict__ dones) {
    __shared__ int hist[512];
    __shared__ int scn[512];
    __shared__ int cur[512];
    int tid = threadIdx.x;
    hist[tid] = 0; cur[tid] = 0;
    __syncthreads();
    if (tid < 256) {
        int b = tid, age = 0;
#pragma unroll 4
        for (int t = 0; t < TT; t++) {
            int d = dones[t * BB + b];
            age = d ? 0 : (t == 0 ? 1 : age + 1);
            if (age > 0) atomicAdd(&hist[age], 1);
        }
    }
    __syncthreads();
    scn[tid] = hist[tid];
    __syncthreads();
    for (int o = 1; o < 512; o <<= 1) {
        int v = (tid >= o) ? scn[tid - o] : 0;
        __syncthreads();
        scn[tid] += v;
        __syncthreads();
    }
    if (tid == 0) g_offs[0] = 0;
    g_offs[tid + 1] = scn[tid];
    __syncthreads();
    if (tid < 256) {
        int b = tid, age = 0;
#pragma unroll 4
        for (int t = 0; t < TT; t++) {
            int d = dones[t * BB + b];
            age = d ? 0 : (t == 0 ? 1 : age + 1);
            if (age > 0) {
                int pos = atomicAdd(&cur[age], 1);
                g_list[(scn[age] - hist[age]) + pos] = t * BB + b;
            }
        }
    }
}

// =====================================================================
// prep / epilogue kernels
// =====================================================================
__global__ void prep_wsplit(const float* __restrict__ W,
                            __nv_bfloat16* __restrict__ hiT,
                            __nv_bfloat16* __restrict__ loT, int K, int N) {
    int n = blockIdx.x;
    for (int k = threadIdx.x; k < K; k += blockDim.x) {
        float x = W[(size_t)k * N + n];
        __nv_bfloat16 h = __float2bfloat16(x);
        hiT[(size_t)n * K + k] = h;
        loT[(size_t)n * K + k] = __float2bfloat16(x - __bfloat162float(h));
    }
}

__global__ void prep_heads_split(const float* __restrict__ Wl1, const float* __restrict__ bl1,
                                 const float* __restrict__ Wl2, const float* __restrict__ bl2,
                                 const float* __restrict__ Wmc, const float* __restrict__ bmc,
                                 const float* __restrict__ Wht, const float* __restrict__ bht,
                                 const float* __restrict__ ba, const float* __restrict__ bc1) {
    int k = blockIdx.x, n = threadIdx.x;
    float v = 0.f, bv = 0.f;
    if (n < 32)       { v = Wl1[k * 32 + n];        bv = bl1[n]; }
    else if (n < 64)  { v = Wl2[k * 32 + (n - 32)]; bv = bl2[n - 32]; }
    else if (n < 80)  { v = Wmc[k * 16 + (n - 64)]; bv = bmc[n - 64]; }
    else if (n < 144) { v = Wht[k * 64 + (n - 80)]; bv = bht[n - 80]; }
    __nv_bfloat16 h = __float2bfloat16(v);
    g_WhdHi[(size_t)n * HH + k] = h;
    g_WhdLo[(size_t)n * HH + k] = __float2bfloat16(v - __bfloat162float(h));
    if (k == 0) {
        g_bheadP[n] = bv;
        g_bac[n] = ba[n];
        g_bac[256 + n] = bc1[n];
    }
}

__global__ void copy_init(const float* __restrict__ hidden) {
    int i = blockIdx.x * 256 + threadIdx.x;
    g_yx[i] = hidden[i];
}

__global__ void copy_hidden(float* __restrict__ out) {
    int i = blockIdx.x * 256 + threadIdx.x;
    out[i] = g_yx[(size_t)MM * HH + i];
}

// =====================================================================
extern "C" void kernel_launch(void* const* d_in, const int* in_sizes, int n_in,
                              void* d_out, int out_size) {
    const float* hidden = (const float*)d_in[0];
    const float* obs    = (const float*)d_in[1];
    const int*   dones  = (const int*)  d_in[2];
    const int*   a_lc1  = (const int*)  d_in[3];
    const int*   a_lc2  = (const int*)  d_in[4];
    const int*   a_mc   = (const int*)  d_in[5];
    const int*   a_hint = (const int*)  d_in[6];
    const float* W_emb  = (const float*)d_in[7];
    const float* b_emb  = (const float*)d_in[8];
    const float* Wi     = (const float*)d_in[9];
    const float* bi     = (const float*)d_in[10];
    const float* Wh     = (const float*)d_in[11];
    const float* bhn    = (const float*)d_in[12];
    const float* W_a    = (const float*)d_in[13];
    const float* b_a    = (const float*)d_in[14];
    const float* W_lc1  = (const float*)d_in[15];
    const float* b_lc1  = (const float*)d_in[16];
    const float* W_lc2  = (const float*)d_in[17];
    const float* b_lc2  = (const float*)d_in[18];
    const float* W_mc   = (const float*)d_in[19];
    const float* b_mc   = (const float*)d_in[20];
    const float* W_hint = (const float*)d_in[21];
    const float* b_hint = (const float*)d_in[22];
    const float* W_c1   = (const float*)d_in[23];
    const float* b_c1   = (const float*)d_in[24];
    const float* W_c2   = (const float*)d_in[25];
    const float* b_c2   = (const float*)d_in[26];
    float* out = (float*)d_out;

    float *p_emb, *p_gi, *p_yx, *p_a, *p_bheadP, *p_bac;
    __nv_bfloat16 *p_WembHi, *p_WembLo, *p_WiHi, *p_WiLo,
                  *p_WacHi, *p_WacLo, *p_WhdHi, *p_WhdLo, *p_WhHi, *p_WhLo;
    cudaGetSymbolAddress((void**)&p_emb, g_emb);
    cudaGetSymbolAddress((void**)&p_gi,  g_gi);
    cudaGetSymbolAddress((void**)&p_yx,  g_yx);
    cudaGetSymbolAddress((void**)&p_a,   g_a);
    cudaGetSymbolAddress((void**)&p_bheadP, g_bheadP);
    cudaGetSymbolAddress((void**)&p_bac, g_bac);
    cudaGetSymbolAddress((void**)&p_WembHi, g_WembHi);
    cudaGetSymbolAddress((void**)&p_WembLo, g_WembLo);
    cudaGetSymbolAddress((void**)&p_WiHi, g_WiHi);
    cudaGetSymbolAddress((void**)&p_WiLo, g_WiLo);
    cudaGetSymbolAddress((void**)&p_WacHi, g_WacHi);
    cudaGetSymbolAddress((void**)&p_WacLo, g_WacLo);
    cudaGetSymbolAddress((void**)&p_WhdHi, g_WhdHi);
    cudaGetSymbolAddress((void**)&p_WhdLo, g_WhdLo);
    cudaGetSymbolAddress((void**)&p_WhHi, g_WhHi);
    cudaGetSymbolAddress((void**)&p_WhLo, g_WhLo);
    const float* p_y = p_yx + (size_t)BB * HH;

    // emb bf16 halves live inside g_emb (134 MB fp32 = 2 x 67 MB bf16)
    __nv_bfloat16* p_embHi = (__nv_bfloat16*)p_emb;
    __nv_bfloat16* p_embLo = p_embHi + (size_t)MM * HH;

    cudaFuncSetAttribute(hgemm<2>, cudaFuncAttributeMaxDynamicSharedMemorySize, HG_SMEM);
    cudaFuncSetAttribute(hgemm<4>, cudaFuncAttributeMaxDynamicSharedMemorySize, HG_SMEM);
    cudaFuncSetAttribute(hgemm<5>, cudaFuncAttributeMaxDynamicSharedMemorySize, HG_SMEM);
    cudaFuncSetAttribute(hgemm_ps, cudaFuncAttributeMaxDynamicSharedMemorySize, HG_SMEM);
    cudaFuncSetAttribute(wave_fused, cudaFuncAttributeMaxDynamicSharedMemorySize, WV_SMEM);

    // ---- prep ----
    build_index<<<1, 512>>>(dones);
    prep_wsplit<<<HH, 256>>>(W_emb, p_WembHi, p_WembLo, OBSD, HH);
    prep_wsplit<<<H3, 256>>>(Wi, p_WiHi, p_WiLo, HH, H3);
    prep_wsplit<<<H3, 256>>>(Wh, p_WhHi, p_WhLo, HH, H3);
    prep_wsplit<<<HH, 256>>>(W_a, p_WacHi, p_WacLo, HH, HH);
    prep_wsplit<<<HH, 256>>>(W_c1, p_WacHi + (size_t)256 * HH, p_WacLo + (size_t)256 * HH, HH, HH);
    prep_heads_split<<<HH, 256>>>(W_lc1, b_lc1, W_lc2, b_lc2, W_mc, b_mc, W_hint, b_hint,
                                  b_a, b_c1);
    copy_init<<<(BB * HH) / 256, 256>>>(hidden);

    // ---- dense front GEMMs ----
    // emb = relu(obs @ W_emb + b) stored as bf16 hi/lo
    hgemm<5><<<dim3(HH / 64, MM / 128), 256, HG_SMEM>>>(obs, p_WembHi, p_WembLo, b_emb,
                                                        (float*)p_embHi, HH, OBSD,
                                                        nullptr, nullptr, nullptr, nullptr,
                                                        nullptr, (float*)p_embLo);
    // gi = emb @ Wi + bi with pre-split A
    hgemm_ps<<<dim3(H3 / 64, MM / 128), 256, HG_SMEM>>>(p_embHi, p_embLo, p_WiHi, p_WiLo,
                                                        bi, p_gi, H3, HH);

    // ---- wavefront GRU ----
    gate_wave0<<<MM / 16, 256>>>(dones, bhn);
    for (int a = 1; a < AMAX; a++) {
        int mb = BB * ((TT + a) / (a + 1));
        int gm = (mb + 127) / 128;
        wave_fused<<<dim3(HH / 32, gm), 256, WV_SMEM>>>(p_WhHi, p_WhLo, bhn, a);
    }

    // ---- dense back GEMMs with fused epilogues ----
    hgemm<4><<<dim3(8, MM / 128), 256, HG_SMEM>>>(p_y, p_WacHi, p_WacLo, p_bac, p_a, 512, HH,
                                                  nullptr, nullptr, nullptr, nullptr, W_c2, nullptr);
    hgemm<2><<<dim3(3, MM / 128), 256, HG_SMEM>>>(p_a, p_WhdHi, p_WhdLo, p_bheadP, nullptr, 256, HH,
                                                  a_lc1, a_lc2, a_mc, a_hint, nullptr, out);

    crit_final<<<MM / 256, 256>>>(b_c2, out);
    copy_hidden<<<(BB * HH) / 256, 256>>>(out);
}

// round 17
// speedup vs baseline: 1.0315x; 1.0315x over previous
#include <cuda_runtime.h>
#include <cuda_bf16.h>
#include <math.h>
#include <stdint.h>

typedef unsigned long long ull;

#define TT 512
#define BB 256
#define OBSD 512
#define HH 256
#define H3 768
#define MM (TT*BB)          // 131072
#define BIGC 1e10f
#define AMAX 48

// hgemm dynamic smem layout (elements, per buffer)
#define HG_BUF   15360
#define HG_ALO   5120
#define HG_BHI   10240
#define HG_BLO   12800
#define HG_SMEM  (2 * HG_BUF * 2)   // 61440 B

// wave_fused dynamic smem layout (elements, per buffer)
#define WV_BUF   17920
#define WV_ALO   5120
#define WV_BHI   10240
#define WV_BLO   14080
#define WV_SMEM  (2 * WV_BUF * 2)   // 71680 B

// ---- output layout ----
static const size_t OFF_LC1  = 65536;
static const size_t OFF_LC2  = OFF_LC1  + (size_t)MM*32;
static const size_t OFF_MC   = OFF_LC2  + (size_t)MM*32;
static const size_t OFF_HINT = OFF_MC   + (size_t)MM*16;
static const size_t OFF_CRIT = OFF_HINT + (size_t)MM*64;

// ---- scratch ----
__device__ float g_emb[(size_t)MM*HH];
__device__ float g_gi [(size_t)MM*H3];
__device__ float g_yx [((size_t)MM+BB)*HH];   // rows 0..B-1: init hidden; row B+i: y_i
__device__ float g_a  [(size_t)MM*HH];
__device__ float g_crit8[(size_t)MM*8];
__device__ float g_bheadP[256];
__device__ float g_bac[512];

// bf16 hi/lo transposed weights [N][K]
__device__ __nv_bfloat16 g_WembHi[HH*OBSD], g_WembLo[HH*OBSD];
__device__ __nv_bfloat16 g_WiHi [H3*HH],   g_WiLo [H3*HH];
__device__ __nv_bfloat16 g_WacHi[512*HH],  g_WacLo[512*HH];
__device__ __nv_bfloat16 g_WhdHi[256*HH],  g_WhdLo[256*HH];
__device__ __nv_bfloat16 g_WhHi [H3*HH],   g_WhLo [H3*HH];

__device__ int g_list[MM];
__device__ int g_offs[513];

// ---- math helpers ----
__device__ __forceinline__ float sigm(float x) {
    return __fdividef(1.f, 1.f + __expf(-x));
}
__device__ __forceinline__ float tanh_fast(float x) {
    return 1.f - __fdividef(2.f, __expf(2.f * x) + 1.f);
}

// ---- mma.sync helpers ----
__device__ __forceinline__ uint32_t smem_u32(const void* p) {
    return (uint32_t)__cvta_generic_to_shared(p);
}
__device__ __forceinline__ void ldsm4(uint32_t* r, uint32_t addr) {
    asm volatile("ldmatrix.sync.aligned.m8n8.x4.shared.b16 {%0,%1,%2,%3}, [%4];"
                 : "=r"(r[0]), "=r"(r[1]), "=r"(r[2]), "=r"(r[3]) : "r"(addr));
}
__device__ __forceinline__ void mma_bf16(float* d, const uint32_t* a, const uint32_t* b) {
    asm volatile(
        "mma.sync.aligned.m16n8k16.row.col.f32.bf16.bf16.f32 "
        "{%0,%1,%2,%3}, {%4,%5,%6,%7}, {%8,%9}, {%0,%1,%2,%3};"
        : "+f"(d[0]), "+f"(d[1]), "+f"(d[2]), "+f"(d[3])
        : "r"(a[0]), "r"(a[1]), "r"(a[2]), "r"(a[3]), "r"(b[0]), "r"(b[1]));
}
__device__ __forceinline__ void split2(float x, float y, __nv_bfloat162& hi, __nv_bfloat162& lo) {
    hi = __floats2bfloat162_rn(x, y);
    lo = __floats2bfloat162_rn(x - __bfloat162float(hi.x), y - __bfloat162float(hi.y));
}

// =====================================================================
// Dense tensor-core bf16-split GEMM (double-buffered, R14/R15 proven).
// MODE 0: store; 1: relu store; 2: head mask+scatter; 4: Wa+c1 merged.
// =====================================================================
template <int MODE>
__global__ __launch_bounds__(256, 2) void hgemm(
    const float* __restrict__ A,
    const __nv_bfloat16* __restrict__ BhiT, const __nv_bfloat16* __restrict__ BloT,
    const float* __restrict__ bias, float* __restrict__ C, int N, int K,
    const int* __restrict__ al1, const int* __restrict__ al2,
    const int* __restrict__ amc, const int* __restrict__ aht,
    const float* __restrict__ w2, float* __restrict__ outp)
{
    extern __shared__ __nv_bfloat16 sm[];

    const int tid = threadIdx.x;
    const int lane = tid & 31;
    const int wid = tid >> 5;
    const int wm = (wid & 3) * 32;
    const int wn = (wid >> 2) * 32;
    const int m0 = blockIdx.y * 128;
    const int n0 = blockIdx.x * 64;

    const int ar = tid >> 3, ac4 = tid & 7;
    const int br = tid >> 2, bs = tid & 3;

    float acc[2][4][4];
#pragma unroll
    for (int mt = 0; mt < 2; mt++)
#pragma unroll
        for (int nt = 0; nt < 4; nt++)
#pragma unroll
            for (int q = 0; q < 4; q++) acc[mt][nt][q] = 0.f;

    float4 ra[4]; uint4 rbh, rbl;
    auto loadg = [&](int kc) {
#pragma unroll
        for (int u = 0; u < 4; u++)
            ra[u] = *(const float4*)&A[(size_t)(m0 + ar + u * 32) * K + kc + ac4 * 4];
        rbh = *(const uint4*)&BhiT[(size_t)(n0 + br) * K + kc + bs * 8];
        rbl = *(const uint4*)&BloT[(size_t)(n0 + br) * K + kc + bs * 8];
    };
    auto storesm = [&](int p) {
        __nv_bfloat16* buf = sm + p * HG_BUF;
#pragma unroll
        for (int u = 0; u < 4; u++) {
            float4 v = ra[u];
            __nv_bfloat162 h0, l0, h1, l1;
            split2(v.x, v.y, h0, l0);
            split2(v.z, v.w, h1, l1);
            union { __nv_bfloat162 b2[2]; ull u64; } ph, pl;
            ph.b2[0] = h0; ph.b2[1] = h1;
            pl.b2[0] = l0; pl.b2[1] = l1;
            *(ull*)&buf[(ar + u * 32) * 40 + ac4 * 4] = ph.u64;
            *(ull*)&buf[HG_ALO + (ar + u * 32) * 40 + ac4 * 4] = pl.u64;
        }
        *(uint4*)&buf[HG_BHI + br * 40 + bs * 8] = rbh;
        *(uint4*)&buf[HG_BLO + br * 40 + bs * 8] = rbl;
    };

    loadg(0);
    storesm(0);
    __syncthreads();

    const int nc = K >> 5;
    for (int i = 0; i < nc; i++) {
        const bool more = (i + 1) < nc;
        if (more) loadg((i + 1) * 32);

        const __nv_bfloat16* buf = sm + (i & 1) * HG_BUF;
#pragma unroll
        for (int kk = 0; kk < 32; kk += 16) {
            uint32_t ah[2][4], al[2][4], bh[4][2], bl[4][2];
            const int arow = (lane & 15);
            const int acol = kk + ((lane >> 4) << 3);
#pragma unroll
            for (int mt = 0; mt < 2; mt++) {
                ldsm4(ah[mt], smem_u32(&buf[(wm + mt * 16 + arow) * 40 + acol]));
                ldsm4(al[mt], smem_u32(&buf[HG_ALO + (wm + mt * 16 + arow) * 40 + acol]));
            }
            const int brow = ((lane >> 4) << 3) + (lane & 7);
            const int bcol = kk + ((lane >> 3) & 1) * 8;
#pragma unroll
            for (int half = 0; half < 2; half++) {
                uint32_t t4[4];
                ldsm4(t4, smem_u32(&buf[HG_BHI + (wn + half * 16 + brow) * 40 + bcol]));
                bh[half*2+0][0] = t4[0]; bh[half*2+0][1] = t4[1];
                bh[half*2+1][0] = t4[2]; bh[half*2+1][1] = t4[3];
                ldsm4(t4, smem_u32(&buf[HG_BLO + (wn + half * 16 + brow) * 40 + bcol]));
                bl[half*2+0][0] = t4[0]; bl[half*2+0][1] = t4[1];
                bl[half*2+1][0] = t4[2]; bl[half*2+1][1] = t4[3];
            }
#pragma unroll
            for (int mt = 0; mt < 2; mt++)
#pragma unroll
                for (int nt = 0; nt < 4; nt++) {
                    mma_bf16(acc[mt][nt], ah[mt], bh[nt]);
                    mma_bf16(acc[mt][nt], al[mt], bh[nt]);
                    mma_bf16(acc[mt][nt], ah[mt], bl[nt]);
                }
        }

        if (more) {
            storesm((i + 1) & 1);
            __syncthreads();
        }
    }

    if (MODE <= 1) {
#pragma unroll
        for (int mt = 0; mt < 2; mt++) {
#pragma unroll
            for (int nt = 0; nt < 4; nt++) {
                int r = m0 + wm + mt * 16 + (lane >> 2);
                int cI = n0 + wn + nt * 8 + (lane & 3) * 2;
                float bx = bias[cI], by = bias[cI + 1];
                float x0 = acc[mt][nt][0] + bx, y0 = acc[mt][nt][1] + by;
                float x1 = acc[mt][nt][2] + bx, y1 = acc[mt][nt][3] + by;
                if (MODE == 1) {
                    x0 = fmaxf(x0, 0.f); y0 = fmaxf(y0, 0.f);
                    x1 = fmaxf(x1, 0.f); y1 = fmaxf(y1, 0.f);
                }
                *(float2*)&C[(size_t)r * N + cI] = make_float2(x0, y0);
                *(float2*)&C[(size_t)(r + 8) * N + cI] = make_float2(x1, y1);
            }
        }
    } else if (MODE == 2) {
        auto emit = [&](int m, int n, float x, float y) {
            if (n < 32) {
                size_t o = (size_t)m * 32 + n;
                outp[OFF_LC1 + o]     = x - (1.f - (float)al1[o]) * BIGC;
                outp[OFF_LC1 + o + 1] = y - (1.f - (float)al1[o + 1]) * BIGC;
            } else if (n < 64) {
                size_t o = (size_t)m * 32 + (n - 32);
                outp[OFF_LC2 + o]     = x - (1.f - (float)al2[o]) * BIGC;
                outp[OFF_LC2 + o + 1] = y - (1.f - (float)al2[o + 1]) * BIGC;
            } else if (n < 80) {
                size_t o = (size_t)m * 16 + (n - 64);
                outp[OFF_MC + o]      = x - (1.f - (float)amc[o]) * BIGC;
                outp[OFF_MC + o + 1]  = y - (1.f - (float)amc[o + 1]) * BIGC;
            } else if (n < 144) {
                size_t o = (size_t)m * 64 + (n - 80);
                outp[OFF_HINT + o]     = x - (1.f - (float)aht[o]) * BIGC;
                outp[OFF_HINT + o + 1] = y - (1.f - (float)aht[o + 1]) * BIGC;
            }
        };
#pragma unroll
        for (int mt = 0; mt < 2; mt++) {
#pragma unroll
            for (int nt = 0; nt < 4; nt++) {
                int r = m0 + wm + mt * 16 + (lane >> 2);
                int cI = n0 + wn + nt * 8 + (lane & 3) * 2;
                float bx = bias[cI], by = bias[cI + 1];
                emit(r,     cI, acc[mt][nt][0] + bx, acc[mt][nt][1] + by);
                emit(r + 8, cI, acc[mt][nt][2] + bx, acc[mt][nt][3] + by);
            }
        }
    } else {
        if (n0 < 256) {
#pragma unroll
            for (int mt = 0; mt < 2; mt++) {
#pragma unroll
                for (int nt = 0; nt < 4; nt++) {
                    int r = m0 + wm + mt * 16 + (lane >> 2);
                    int cI = n0 + wn + nt * 8 + (lane & 3) * 2;
                    float bx = bias[cI], by = bias[cI + 1];
                    float x0 = fmaxf(acc[mt][nt][0] + bx, 0.f);
                    float y0 = fmaxf(acc[mt][nt][1] + by, 0.f);
                    float x1 = fmaxf(acc[mt][nt][2] + bx, 0.f);
                    float y1 = fmaxf(acc[mt][nt][3] + by, 0.f);
                    *(float2*)&C[(size_t)r * 256 + cI] = make_float2(x0, y0);
                    *(float2*)&C[(size_t)(r + 8) * 256 + cI] = make_float2(x1, y1);
                }
            }
        } else {
#pragma unroll
            for (int mt = 0; mt < 2; mt++) {
#pragma unroll
                for (int rr = 0; rr < 2; rr++) {
                    float partial = 0.f;
#pragma unroll
                    for (int nt = 0; nt < 4; nt++) {
                        int cI = n0 + wn + nt * 8 + (lane & 3) * 2;
                        float x = fmaxf(acc[mt][nt][rr*2+0] + bias[cI], 0.f);
                        float y = fmaxf(acc[mt][nt][rr*2+1] + bias[cI+1], 0.f);
                        partial = fmaf(x, w2[cI - 256], partial);
                        partial = fmaf(y, w2[cI - 255], partial);
                    }
                    partial += __shfl_xor_sync(0xffffffffu, partial, 1);
                    partial += __shfl_xor_sync(0xffffffffu, partial, 2);
                    if ((lane & 3) == 0) {
                        int r = m0 + wm + mt * 16 + (lane >> 2) + rr * 8;
                        g_crit8[(size_t)r * 8 + (blockIdx.x - 4) * 2 + (wid >> 2)] = partial;
                    }
                }
            }
        }
    }
}

// merged critic finalize + hidden copy (one launch)
__global__ void finalize(const float* __restrict__ b2, float* __restrict__ out) {
    int bid = blockIdx.x;
    if (bid < MM / 256) {
        int m = bid * 256 + threadIdx.x;
        const float4* p = (const float4*)&g_crit8[(size_t)m * 8];
        float4 v0 = p[0], v1 = p[1];
        out[OFF_CRIT + m] = v0.x + v0.y + v0.z + v0.w + v1.x + v1.y + v1.z + v1.w + b2[0];
    } else {
        int i = (bid - MM / 256) * 256 + threadIdx.x;
        out[i] = g_yx[(size_t)MM * HH + i];
    }
}

// =====================================================================
// Fused wave kernel (double-buffered, R15 proven).
// =====================================================================
__global__ __launch_bounds__(256, 2) void wave_fused(
    const __nv_bfloat16* __restrict__ WhHiT, const __nv_bfloat16* __restrict__ WhLoT,
    const float* __restrict__ bhn, int a)
{
    const int base = g_offs[a];
    const int cnt  = g_offs[a + 1] - base;
    const int m0 = blockIdx.y * 128;
    if (m0 >= cnt) return;
    const int j0 = blockIdx.x * 32;

    extern __shared__ __nv_bfloat16 sm[];

    const int tid = threadIdx.x;
    const int lane = tid & 31;
    const int wid = tid >> 5;
    const int wm = (wid & 3) * 32;
    const int wn = (wid >> 2) * 16;

    const int ar = tid >> 3, ac4 = tid & 7;
    int ridx[4];
#pragma unroll
    for (int u = 0; u < 4; u++) {
        int m = m0 + ar + u * 32;
        ridx[u] = g_list[base + (m < cnt ? m : cnt - 1)];
    }
    const int br0 = tid >> 2, bs0 = tid & 3;
    const int br1 = 64 + (tid >> 2), bs1 = tid & 3;
    const int bgr0 = (br0 >> 5) * HH + j0 + (br0 & 31);
    const int bgr1 = (br1 >> 5) * HH + j0 + (br1 & 31);

    float acc[3][2][2][4];
#pragma unroll
    for (int g = 0; g < 3; g++)
#pragma unroll
        for (int mt = 0; mt < 2; mt++)
#pragma unroll
            for (int nt = 0; nt < 2; nt++)
#pragma unroll
                for (int q = 0; q < 4; q++) acc[g][mt][nt][q] = 0.f;

    float4 ra[4]; uint4 rbh0, rbl0, rbh1, rbl1;
    auto loadg = [&](int kc) {
#pragma unroll
        for (int u = 0; u < 4; u++)
            ra[u] = *(const float4*)&g_yx[(size_t)ridx[u] * HH + kc + ac4 * 4];
        rbh0 = *(const uint4*)&WhHiT[(size_t)bgr0 * HH + kc + bs0 * 8];
        rbl0 = *(const uint4*)&WhLoT[(size_t)bgr0 * HH + kc + bs0 * 8];
        if (tid < 128) {
            rbh1 = *(const uint4*)&WhHiT[(size_t)bgr1 * HH + kc + bs1 * 8];
            rbl1 = *(const uint4*)&WhLoT[(size_t)bgr1 * HH + kc + bs1 * 8];
        }
    };
    auto storesm = [&](int p) {
        __nv_bfloat16* buf = sm + p * WV_BUF;
#pragma unroll
        for (int u = 0; u < 4; u++) {
            float4 v = ra[u];
            __nv_bfloat162 h0, l0, h1, l1;
            split2(v.x, v.y, h0, l0);
            split2(v.z, v.w, h1, l1);
            union { __nv_bfloat162 b2[2]; ull u64; } ph, pl;
            ph.b2[0] = h0; ph.b2[1] = h1;
            pl.b2[0] = l0; pl.b2[1] = l1;
            *(ull*)&buf[(ar + u * 32) * 40 + ac4 * 4] = ph.u64;
            *(ull*)&buf[WV_ALO + (ar + u * 32) * 40 + ac4 * 4] = pl.u64;
        }
        *(uint4*)&buf[WV_BHI + br0 * 40 + bs0 * 8] = rbh0;
        *(uint4*)&buf[WV_BLO + br0 * 40 + bs0 * 8] = rbl0;
        if (tid < 128) {
            *(uint4*)&buf[WV_BHI + br1 * 40 + bs1 * 8] = rbh1;
            *(uint4*)&buf[WV_BLO + br1 * 40 + bs1 * 8] = rbl1;
        }
    };

    loadg(0);
    storesm(0);
    __syncthreads();

    const int nc = HH >> 5;
    for (int i = 0; i < nc; i++) {
        const bool more = (i + 1) < nc;
        if (more) loadg((i + 1) * 32);

        const __nv_bfloat16* buf = sm + (i & 1) * WV_BUF;
#pragma unroll
        for (int kk = 0; kk < 32; kk += 16) {
            uint32_t ah[2][4], al[2][4];
            const int arow = (lane & 15);
            const int acol = kk + ((lane >> 4) << 3);
#pragma unroll
            for (int mt = 0; mt < 2; mt++) {
                ldsm4(ah[mt], smem_u32(&buf[(wm + mt * 16 + arow) * 40 + acol]));
                ldsm4(al[mt], smem_u32(&buf[WV_ALO + (wm + mt * 16 + arow) * 40 + acol]));
            }
            const int brow = ((lane >> 4) << 3) + (lane & 7);
            const int bcol = kk + ((lane >> 3) & 1) * 8;
#pragma unroll
            for (int g = 0; g < 3; g++) {
                uint32_t bh[4], bl[4];
                ldsm4(bh, smem_u32(&buf[WV_BHI + (g * 32 + wn + brow) * 40 + bcol]));
                ldsm4(bl, smem_u32(&buf[WV_BLO + (g * 32 + wn + brow) * 40 + bcol]));
#pragma unroll
                for (int mt = 0; mt < 2; mt++) {
                    mma_bf16(acc[g][mt][0], ah[mt], bh + 0);
                    mma_bf16(acc[g][mt][1], ah[mt], bh + 2);
                    mma_bf16(acc[g][mt][0], al[mt], bh + 0);
                    mma_bf16(acc[g][mt][1], al[mt], bh + 2);
                    mma_bf16(acc[g][mt][0], ah[mt], bl + 0);
                    mma_bf16(acc[g][mt][1], ah[mt], bl + 2);
                }
            }
        }

        if (more) {
            storesm((i + 1) & 1);
            __syncthreads();
        }
    }

    // fused GRU gate epilogue
#pragma unroll
    for (int mt = 0; mt < 2; mt++) {
#pragma unroll
        for (int nt = 0; nt < 2; nt++) {
            const int jj = j0 + wn + nt * 8 + (lane & 3) * 2;
            const float2 bh2 = *(const float2*)&bhn[jj];
#pragma unroll
            for (int rr = 0; rr < 2; rr++) {
                int m = m0 + wm + mt * 16 + (lane >> 2) + rr * 8;
                if (m >= cnt) continue;
                int idx = g_list[base + m];
                const float* gip = g_gi + (size_t)idx * H3;
                float2 gr2 = *(const float2*)&gip[jj];
                float2 gz2 = *(const float2*)&gip[HH + jj];
                float2 gn2 = *(const float2*)&gip[2 * HH + jj];
                float2 h2  = *(const float2*)&g_yx[(size_t)idx * HH + jj];
                float r0 = sigm(gr2.x + acc[0][mt][nt][rr*2+0]);
                float r1 = sigm(gr2.y + acc[0][mt][nt][rr*2+1]);
                float z0 = sigm(gz2.x + acc[1][mt][nt][rr*2+0]);
                float z1 = sigm(gz2.y + acc[1][mt][nt][rr*2+1]);
                float n0 = tanh_fast(gn2.x + r0 * (acc[2][mt][nt][rr*2+0] + bh2.x));
                float n1 = tanh_fast(gn2.y + r1 * (acc[2][mt][nt][rr*2+1] + bh2.y));
                float y0 = (1.f - z0) * n0 + z0 * h2.x;
                float y1 = (1.f - z1) * n1 + z1 * h2.y;
                *(float2*)&g_yx[(size_t)(idx + BB) * HH + jj] = make_float2(y0, y1);
            }
        }
    }
}

// =====================================================================
// Gate for wave 0 (membership = dones != 0)
// =====================================================================
__global__ void gate_wave0(const int* __restrict__ dones, const float* __restrict__ bhn) {
    int m = blockIdx.x * 16 + (threadIdx.x >> 4);
    if (dones[m] == 0) return;
    int jg = threadIdx.x & 15;
    const float* gip = g_gi + (size_t)m * H3;
    float* yp = g_yx + (size_t)(m + BB) * HH;
#pragma unroll 4
    for (int l = 0; l < 16; l++) {
        int j = l * 16 + jg;
        float r = sigm(gip[j]);
        float z = sigm(gip[HH + j]);
        float n = tanh_fast(gip[2 * HH + j] + r * bhn[j]);
        yp[j] = (1.f - z) * n;
    }
}

// =====================================================================
// Fused index build (ages >= 1 only)
// =====================================================================
__global__ __launch_bounds__(512) void build_index(const int* __restrict__ dones) {
    __shared__ int hist[512];
    __shared__ int scn[512];
    __shared__ int cur[512];
    int tid = threadIdx.x;
    hist[tid] = 0; cur[tid] = 0;
    __syncthreads();
    if (tid < 256) {
        int b = tid, age = 0;
#pragma unroll 4
        for (int t = 0; t < TT; t++) {
            int d = dones[t * BB + b];
            age = d ? 0 : (t == 0 ? 1 : age + 1);
            if (age > 0) atomicAdd(&hist[age], 1);
        }
    }
    __syncthreads();
    scn[tid] = hist[tid];
    __syncthreads();
    for (int o = 1; o < 512; o <<= 1) {
        int v = (tid >= o) ? scn[tid - o] : 0;
        __syncthreads();
        scn[tid] += v;
        __syncthreads();
    }
    if (tid == 0) g_offs[0] = 0;
    g_offs[tid + 1] = scn[tid];
    __syncthreads();
    if (tid < 256) {
        int b = tid, age = 0;
#pragma unroll 4
        for (int t = 0; t < TT; t++) {
            int d = dones[t * BB + b];
            age = d ? 0 : (t == 0 ? 1 : age + 1);
            if (age > 0) {
                int pos = atomicAdd(&cur[age], 1);
                g_list[(scn[age] - hist[age]) + pos] = t * BB + b;
            }
        }
    }
}

// =====================================================================
// prep / epilogue kernels
// =====================================================================
__global__ void prep_wsplit(const float* __restrict__ W,
                            __nv_bfloat16* __restrict__ hiT,
                            __nv_bfloat16* __restrict__ loT, int K, int N) {
    int n = blockIdx.x;
    for (int k = threadIdx.x; k < K; k += blockDim.x) {
        float x = W[(size_t)k * N + n];
        __nv_bfloat16 h = __float2bfloat16(x);
        hiT[(size_t)n * K + k] = h;
        loT[(size_t)n * K + k] = __float2bfloat16(x - __bfloat162float(h));
    }
}

__global__ void prep_heads_split(const float* __restrict__ Wl1, const float* __restrict__ bl1,
                                 const float* __restrict__ Wl2, const float* __restrict__ bl2,
                                 const float* __restrict__ Wmc, const float* __restrict__ bmc,
                                 const float* __restrict__ Wht, const float* __restrict__ bht,
                                 const float* __restrict__ ba, const float* __restrict__ bc1) {
    int k = blockIdx.x, n = threadIdx.x;
    float v = 0.f, bv = 0.f;
    if (n < 32)       { v = Wl1[k * 32 + n];        bv = bl1[n]; }
    else if (n < 64)  { v = Wl2[k * 32 + (n - 32)]; bv = bl2[n - 32]; }
    else if (n < 80)  { v = Wmc[k * 16 + (n - 64)]; bv = bmc[n - 64]; }
    else if (n < 144) { v = Wht[k * 64 + (n - 80)]; bv = bht[n - 80]; }
    __nv_bfloat16 h = __float2bfloat16(v);
    g_WhdHi[(size_t)n * HH + k] = h;
    g_WhdLo[(size_t)n * HH + k] = __float2bfloat16(v - __bfloat162float(h));
    if (k == 0) {
        g_bheadP[n] = bv;
        g_bac[n] = ba[n];
        g_bac[256 + n] = bc1[n];
    }
}

__global__ void copy_init(const float* __restrict__ hidden) {
    int i = blockIdx.x * 256 + threadIdx.x;
    g_yx[i] = hidden[i];
}

// =====================================================================
extern "C" void kernel_launch(void* const* d_in, const int* in_sizes, int n_in,
                              void* d_out, int out_size) {
    const float* hidden = (const float*)d_in[0];
    const float* obs    = (const float*)d_in[1];
    const int*   dones  = (const int*)  d_in[2];
    const int*   a_lc1  = (const int*)  d_in[3];
    const int*   a_lc2  = (const int*)  d_in[4];
    const int*   a_mc   = (const int*)  d_in[5];
    const int*   a_hint = (const int*)  d_in[6];
    const float* W_emb  = (const float*)d_in[7];
    const float* b_emb  = (const float*)d_in[8];
    const float* Wi     = (const float*)d_in[9];
    const float* bi     = (const float*)d_in[10];
    const float* Wh     = (const float*)d_in[11];
    const float* bhn    = (const float*)d_in[12];
    const float* W_a    = (const float*)d_in[13];
    const float* b_a    = (const float*)d_in[14];
    const float* W_lc1  = (const float*)d_in[15];
    const float* b_lc1  = (const float*)d_in[16];
    const float* W_lc2  = (const float*)d_in[17];
    const float* b_lc2  = (const float*)d_in[18];
    const float* W_mc   = (const float*)d_in[19];
    const float* b_mc   = (const float*)d_in[20];
    const float* W_hint = (const float*)d_in[21];
    const float* b_hint = (const float*)d_in[22];
    const float* W_c1   = (const float*)d_in[23];
    const float* b_c1   = (const float*)d_in[24];
    const float* W_c2   = (const float*)d_in[25];
    const float* b_c2   = (const float*)d_in[26];
    float* out = (float*)d_out;

    float *p_emb, *p_gi, *p_yx, *p_a, *p_bheadP, *p_bac;
    __nv_bfloat16 *p_WembHi, *p_WembLo, *p_WiHi, *p_WiLo,
                  *p_WacHi, *p_WacLo, *p_WhdHi, *p_WhdLo, *p_WhHi, *p_WhLo;
    cudaGetSymbolAddress((void**)&p_emb, g_emb);
    cudaGetSymbolAddress((void**)&p_gi,  g_gi);
    cudaGetSymbolAddress((void**)&p_yx,  g_yx);
    cudaGetSymbolAddress((void**)&p_a,   g_a);
    cudaGetSymbolAddress((void**)&p_bheadP, g_bheadP);
    cudaGetSymbolAddress((void**)&p_bac, g_bac);
    cudaGetSymbolAddress((void**)&p_WembHi, g_WembHi);
    cudaGetSymbolAddress((void**)&p_WembLo, g_WembLo);
    cudaGetSymbolAddress((void**)&p_WiHi, g_WiHi);
    cudaGetSymbolAddress((void**)&p_WiLo, g_WiLo);
    cudaGetSymbolAddress((void**)&p_WacHi, g_WacHi);
    cudaGetSymbolAddress((void**)&p_WacLo, g_WacLo);
    cudaGetSymbolAddress((void**)&p_WhdHi, g_WhdHi);
    cudaGetSymbolAddress((void**)&p_WhdLo, g_WhdLo);
    cudaGetSymbolAddress((void**)&p_WhHi, g_WhHi);
    cudaGetSymbolAddress((void**)&p_WhLo, g_WhLo);
    const float* p_y = p_yx + (size_t)BB * HH;

    cudaFuncSetAttribute(hgemm<0>, cudaFuncAttributeMaxDynamicSharedMemorySize, HG_SMEM);
    cudaFuncSetAttribute(hgemm<1>, cudaFuncAttributeMaxDynamicSharedMemorySize, HG_SMEM);
    cudaFuncSetAttribute(hgemm<2>, cudaFuncAttributeMaxDynamicSharedMemorySize, HG_SMEM);
    cudaFuncSetAttribute(hgemm<4>, cudaFuncAttributeMaxDynamicSharedMemorySize, HG_SMEM);
    cudaFuncSetAttribute(wave_fused, cudaFuncAttributeMaxDynamicSharedMemorySize, WV_SMEM);

    // ---- prep ----
    build_index<<<1, 512>>>(dones);
    prep_wsplit<<<HH, 256>>>(W_emb, p_WembHi, p_WembLo, OBSD, HH);
    prep_wsplit<<<H3, 256>>>(Wi, p_WiHi, p_WiLo, HH, H3);
    prep_wsplit<<<H3, 256>>>(Wh, p_WhHi, p_WhLo, HH, H3);
    prep_wsplit<<<HH, 256>>>(W_a, p_WacHi, p_WacLo, HH, HH);
    prep_wsplit<<<HH, 256>>>(W_c1, p_WacHi + (size_t)256 * HH, p_WacLo + (size_t)256 * HH, HH, HH);
    prep_heads_split<<<HH, 256>>>(W_lc1, b_lc1, W_lc2, b_lc2, W_mc, b_mc, W_hint, b_hint,
                                  b_a, b_c1);
    copy_init<<<(BB * HH) / 256, 256>>>(hidden);

    // ---- dense front GEMMs (double-buffered) ----
    hgemm<1><<<dim3(HH / 64, MM / 128), 256, HG_SMEM>>>(obs, p_WembHi, p_WembLo, b_emb, p_emb, HH, OBSD,
                                                        nullptr, nullptr, nullptr, nullptr, nullptr, nullptr);
    hgemm<0><<<dim3(H3 / 64, MM / 128), 256, HG_SMEM>>>(p_emb, p_WiHi, p_WiLo, bi, p_gi, H3, HH,
                                                        nullptr, nullptr, nullptr, nullptr, nullptr, nullptr);

    // ---- wavefront GRU (per-wave launches, double-buffered tiles) ----
    gate_wave0<<<MM / 16, 256>>>(dones, bhn);
    for (int a = 1; a < AMAX; a++) {
        int mb = BB * ((TT + a) / (a + 1));
        int gm = (mb + 127) / 128;
        wave_fused<<<dim3(HH / 32, gm), 256, WV_SMEM>>>(p_WhHi, p_WhLo, bhn, a);
    }

    // ---- dense back GEMMs with fused epilogues ----
    hgemm<4><<<dim3(8, MM / 128), 256, HG_SMEM>>>(p_y, p_WacHi, p_WacLo, p_bac, p_a, 512, HH,
                                                  nullptr, nullptr, nullptr, nullptr, W_c2, nullptr);
    hgemm<2><<<dim3(3, MM / 128), 256, HG_SMEM>>>(p_a, p_WhdHi, p_WhdLo, p_bheadP, nullptr, 256, HH,
                                                  a_lc1, a_lc2, a_mc, a_hint, nullptr, out);

    finalize<<<MM / 256 + (BB * HH) / 256, 256>>>(b_c2, out);
}